// round 7
// baseline (speedup 1.0000x reference)
#include <cuda_runtime.h>
#include <cstdint>

// Problem constants
#define BB 1024
#define NN 4096
#define NTH 128
#define NWARP (NTH / 32)
#define NACC 23

#define STAGE_PTS   512                       // points per pipeline stage
#define NSTAGE      (NN / STAGE_PTS)          // 8 stages
#define NBUF        2                         // double buffer
#define ARR_BYTES   (STAGE_PTS * 4)           // 2048 B per array per stage
#define STAGE_BYTES (7 * ARR_BYTES)           // 14336 B per stage

// ---------------- PTX helpers ----------------
__device__ __forceinline__ uint32_t smem_u32(const void* p) {
    return (uint32_t)__cvta_generic_to_shared(p);
}
__device__ __forceinline__ void mbar_init(uint32_t mbar, uint32_t count) {
    asm volatile("mbarrier.init.shared.b64 [%0], %1;" :: "r"(mbar), "r"(count) : "memory");
}
__device__ __forceinline__ void mbar_expect_tx(uint32_t mbar, uint32_t bytes) {
    asm volatile("mbarrier.arrive.expect_tx.shared.b64 _, [%0], %1;"
                 :: "r"(mbar), "r"(bytes) : "memory");
}
__device__ __forceinline__ void mbar_arrive(uint32_t mbar) {
    asm volatile("mbarrier.arrive.shared.b64 _, [%0];" :: "r"(mbar) : "memory");
}
__device__ __forceinline__ void mbar_wait(uint32_t mbar, uint32_t parity) {
    asm volatile(
        "{\n\t"
        ".reg .pred P;\n\t"
        "WL_%=:\n\t"
        "mbarrier.try_wait.parity.acquire.cta.shared::cta.b64 P, [%0], %1, 0x989680;\n\t"
        "@P bra.uni WD_%=;\n\t"
        "bra.uni WL_%=;\n\t"
        "WD_%=:\n\t"
        "}"
        :: "r"(mbar), "r"(parity) : "memory");
}
__device__ __forceinline__ void bulk_g2s(uint32_t dst_smem, const void* src, uint32_t bytes,
                                         uint32_t mbar) {
    asm volatile(
        "cp.async.bulk.shared::cluster.global.mbarrier::complete_tx::bytes [%0], [%1], %2, [%3];"
        :: "r"(dst_smem), "l"(src), "r"(bytes), "r"(mbar) : "memory");
}

// Accumulator layout:
//  0..5  : Mw symmetric (00,01,02,11,12,22)
//  6..8  : mw ; 9..11 : yw ; 12..20 : MY[i*3+j] ; 21 : sw ; 22 : yy
__device__ __forceinline__ void accum_point(float acc[NACC],
                                            float m0, float m1, float m2,
                                            float y0, float y1, float y2,
                                            float w) {
    float wm0 = w * m0, wm1 = w * m1, wm2 = w * m2;
    acc[0]  += wm0 * m0;  acc[1]  += wm0 * m1;  acc[2]  += wm0 * m2;
    acc[3]  += wm1 * m1;  acc[4]  += wm1 * m2;  acc[5]  += wm2 * m2;
    acc[6]  += wm0;       acc[7]  += wm1;       acc[8]  += wm2;
    float wy0 = w * y0, wy1 = w * y1, wy2 = w * y2;
    acc[9]  += wy0;       acc[10] += wy1;       acc[11] += wy2;
    acc[12] += wm0 * y0;  acc[13] += wm0 * y1;  acc[14] += wm0 * y2;
    acc[15] += wm1 * y0;  acc[16] += wm1 * y1;  acc[17] += wm1 * y2;
    acc[18] += wm2 * y0;  acc[19] += wm2 * y1;  acc[20] += wm2 * y2;
    acc[21] += w;
    acc[22] += wy0 * y0 + wy1 * y1 + wy2 * y2;
}

__device__ __forceinline__ int sym_idx(int i, int j) {
    if (i > j) { int t = i; i = j; j = t; }
    return i * (5 - i) / 2 + j;
}

__global__ __launch_bounds__(NTH, 7)
void locblock_kernel(const float* __restrict__ src,
                     const float* __restrict__ trg,
                     const float* __restrict__ wts,
                     float* __restrict__ out) {
    const int b   = blockIdx.x;
    const int tid = threadIdx.x;

    // Seven input streams for this batch
    const float* ap[7];
    ap[0] = src + (size_t)b * 3 * NN;          // m0
    ap[1] = ap[0] + NN;                        // m1
    ap[2] = ap[1] + NN;                        // m2
    ap[3] = trg + (size_t)b * 3 * NN;          // y0
    ap[4] = ap[3] + NN;                        // y1
    ap[5] = ap[4] + NN;                        // y2
    ap[6] = wts + (size_t)b * NN;              // w

    __shared__ __align__(16) float buf[NBUF][7][STAGE_PTS];   // 28 KB
    __shared__ __align__(8) uint64_t mb_full[NBUF];
    __shared__ __align__(8) uint64_t mb_empty[NBUF];
    __shared__ float sred[NWARP][NACC];
    __shared__ float fin[NACC];
    __shared__ float s_inv_scale;
    __shared__ float s_scale;

    uint32_t full_a[NBUF], empty_a[NBUF];
#pragma unroll
    for (int s = 0; s < NBUF; s++) {
        full_a[s]  = smem_u32(&mb_full[s]);
        empty_a[s] = smem_u32(&mb_empty[s]);
    }

    if (tid == 0) {
#pragma unroll
        for (int s = 0; s < NBUF; s++) {
            mbar_init(full_a[s], 1);       // completed by expect_tx + TMA tx bytes
            mbar_init(empty_a[s], NTH);    // all threads arrive after consuming
        }
    }
    __syncthreads();

    // Prologue: fill both buffers (no empty-wait needed for first use)
    if (tid == 0) {
#pragma unroll
        for (int s = 0; s < NBUF; s++) {
            mbar_expect_tx(full_a[s], STAGE_BYTES);
#pragma unroll
            for (int a = 0; a < 7; a++)
                bulk_g2s(smem_u32(&buf[s][a][0]), ap[a] + s * STAGE_PTS, ARR_BYTES, full_a[s]);
        }
    }

    float acc[NACC];
#pragma unroll
    for (int k = 0; k < NACC; k++) acc[k] = 0.f;

#pragma unroll
    for (int it = 0; it < NSTAGE; it++) {
        const int bf = it & 1;
        const uint32_t ph = (it >> 1) & 1;

        mbar_wait(full_a[bf], ph);

        // Each thread consumes 4 contiguous points: one float4 per array.
        const int o = tid * 4;
        float4 a0 = *(const float4*)&buf[bf][0][o];
        float4 a1 = *(const float4*)&buf[bf][1][o];
        float4 a2 = *(const float4*)&buf[bf][2][o];
        float4 b0 = *(const float4*)&buf[bf][3][o];
        float4 b1 = *(const float4*)&buf[bf][4][o];
        float4 b2 = *(const float4*)&buf[bf][5][o];
        float4 wv = *(const float4*)&buf[bf][6][o];
        accum_point(acc, a0.x, a1.x, a2.x, b0.x, b1.x, b2.x, wv.x);
        accum_point(acc, a0.y, a1.y, a2.y, b0.y, b1.y, b2.y, wv.y);
        accum_point(acc, a0.z, a1.z, a2.z, b0.z, b1.z, b2.z, wv.z);
        accum_point(acc, a0.w, a1.w, a2.w, b0.w, b1.w, b2.w, wv.w);

        mbar_arrive(empty_a[bf]);

        // Refill this buffer with stage it+2 once all threads have consumed it.
        if (tid == 0 && it + NBUF < NSTAGE) {
            mbar_wait(empty_a[bf], ph);          // phase (it/2) completes after NTH arrivals
            const int ns = it + NBUF;
            mbar_expect_tx(full_a[bf], STAGE_BYTES);
#pragma unroll
            for (int a = 0; a < 7; a++)
                bulk_g2s(smem_u32(&buf[bf][a][0]), ap[a] + ns * STAGE_PTS, ARR_BYTES, full_a[bf]);
        }
    }

    // Intra-warp shuffle reduction
#pragma unroll
    for (int k = 0; k < NACC; k++) {
#pragma unroll
        for (int off = 16; off > 0; off >>= 1)
            acc[k] += __shfl_xor_sync(0xFFFFFFFFu, acc[k], off);
    }

    const int warp = tid >> 5;
    const int lane = tid & 31;
    if (lane == 0) {
#pragma unroll
        for (int k = 0; k < NACC; k++) sred[warp][k] = acc[k];
    }
    __syncthreads();

    if (tid < NACC) {
        float s = 0.f;
#pragma unroll
        for (int wI = 0; wI < NWARP; wI++) s += sred[wI][tid];
        fin[tid] = s;
    }
    __syncthreads();

    if (tid == 0) {
        // scale^2 = 3*sum(Mw^2) + 6*sum(mw^2) + 2*sum(MY^2) + 2*sum(yw^2) + 3*sw^2
        float sumMw2 = fin[0] * fin[0] + fin[3] * fin[3] + fin[5] * fin[5]
                     + 2.f * (fin[1] * fin[1] + fin[2] * fin[2] + fin[4] * fin[4]);
        float summw2 = fin[6] * fin[6] + fin[7] * fin[7] + fin[8] * fin[8];
        float sumyw2 = fin[9] * fin[9] + fin[10] * fin[10] + fin[11] * fin[11];
        float sumMY2 = 0.f;
#pragma unroll
        for (int k = 12; k < 21; k++) sumMY2 += fin[k] * fin[k];
        float sw = fin[21];
        float sc2 = 3.f * sumMw2 + 6.f * summw2 + 2.f * sumMY2 + 2.f * sumyw2 + 3.f * sw * sw;
        float sc = sqrtf(sc2);
        s_scale = sc;
        s_inv_scale = 1.f / sc;
    }
    __syncthreads();

    // Assemble + write Qn
    float* Qn      = out;                           // [B][13][13]
    float* scales  = out + (size_t)BB * 169;        // [B]
    float* offsets = out + (size_t)BB * 169 + BB;   // [B]

    const float inv_sc = s_inv_scale;
    for (int e = tid; e < 169; e += NTH) {
        int r = e / 13;
        int c = e % 13;
        float v = 0.f;
        if (r >= 1 && r <= 9) {
            int a = r - 1;
            int i = a / 3, k = a % 3;
            if (c >= 1 && c <= 9) {
                int bq = c - 1;
                int j = bq / 3, l = bq % 3;
                if (k == l) v = fin[sym_idx(i, j)];       // Qcc
            } else if (c >= 10) {
                int l = c - 10;
                if (k == l) v = -fin[6 + i];              // Qct
            } else {
                v = -fin[12 + i * 3 + k];                 // Qch
            }
        } else if (r >= 10) {
            int i_t = r - 10;
            if (c >= 1 && c <= 9) {
                int a = c - 1;
                int i = a / 3, k = a % 3;
                if (k == i_t) v = -fin[6 + i];            // Qct^T
            } else if (c >= 10) {
                if (r == c) v = fin[21];                  // Qtt
            } else {
                v = fin[9 + i_t];                         // yw
            }
        } else {
            if (c >= 1 && c <= 9) {
                v = -fin[12 + (c - 1)];                   // Qch row
            } else if (c >= 10) {
                v = fin[9 + (c - 10)];                    // yw row
            }
        }
        Qn[(size_t)b * 169 + e] = v * inv_sc;
    }
    if (tid == 0) {
        scales[b]  = s_scale;
        offsets[b] = fin[22];
    }
}

extern "C" void kernel_launch(void* const* d_in, const int* in_sizes, int n_in,
                              void* d_out, int out_size) {
    const float* src = (const float*)d_in[0];
    const float* trg = (const float*)d_in[1];
    const float* wts = (const float*)d_in[2];
    float* out = (float*)d_out;
    locblock_kernel<<<BB, NTH>>>(src, trg, wts, out);
}